// round 3
// baseline (speedup 1.0000x reference)
#include <cuda_runtime.h>
#include <math.h>

#define L_SEQ   2048
#define D_MODEL 2048
#define NHEADS  16
#define DHEAD   128
#define DC      512
#define DCQ     1024
#define QHEADS  32   // 2 * NHEADS

// ---------------------------------------------------------------------------
// Scratch (static device globals -- no runtime allocation allowed)
// ---------------------------------------------------------------------------
__device__ float g_ckv [L_SEQ * DC];            //  4 MB
__device__ float g_k   [L_SEQ * D_MODEL];       // 16 MB  [l][h*128+d]
__device__ float g_v   [L_SEQ * D_MODEL];       // 16 MB
__device__ float g_cq  [L_SEQ * DCQ];           //  8 MB
__device__ float g_q   [L_SEQ * 2 * D_MODEL];   // 32 MB  [l][qh*128+d]
__device__ float g_attn[QHEADS * L_SEQ * DHEAD];// 32 MB  [qh][l][d]
__device__ float g_lam [L_SEQ * NHEADS];
__device__ float g_comb[L_SEQ * D_MODEL];       // 16 MB

// ---------------------------------------------------------------------------
// SGEMM: C[M,N] = A[M,K] @ B[K,N], all row-major, fp32.
// 128x128 tile, BK=16, 256 threads, 8x8 per-thread microtile.
// Requires M%128==0, N%128==0, K%16==0 (true for every call here).
// ---------------------------------------------------------------------------
__global__ __launch_bounds__(256) void sgemm_kernel(
    const float* __restrict__ A, const float* __restrict__ B,
    float* __restrict__ C, int M, int N, int K)
{
    __shared__ float As[16][132];   // transposed A tile, padded
    __shared__ float Bs[16][128];

    const int tid  = threadIdx.x;
    const int tx   = tid & 15;
    const int ty   = tid >> 4;
    const int brow = blockIdx.y * 128;
    const int bcol = blockIdx.x * 128;

    const int a_row = tid >> 2;          // 0..63
    const int a_col = (tid & 3) << 2;    // 0,4,8,12
    const int b_row = tid >> 5;          // 0..7
    const int b_col = (tid & 31) << 2;   // 0..124

    float acc[8][8];
#pragma unroll
    for (int i = 0; i < 8; i++)
#pragma unroll
        for (int j = 0; j < 8; j++) acc[i][j] = 0.f;

    for (int k0 = 0; k0 < K; k0 += 16) {
        float4 a0 = *(const float4*)&A[(size_t)(brow + a_row)      * K + k0 + a_col];
        float4 a1 = *(const float4*)&A[(size_t)(brow + a_row + 64) * K + k0 + a_col];
        float4 b0 = *(const float4*)&B[(size_t)(k0 + b_row)     * N + bcol + b_col];
        float4 b1 = *(const float4*)&B[(size_t)(k0 + b_row + 8) * N + bcol + b_col];

        As[a_col + 0][a_row] = a0.x;  As[a_col + 1][a_row] = a0.y;
        As[a_col + 2][a_row] = a0.z;  As[a_col + 3][a_row] = a0.w;
        As[a_col + 0][a_row + 64] = a1.x;  As[a_col + 1][a_row + 64] = a1.y;
        As[a_col + 2][a_row + 64] = a1.z;  As[a_col + 3][a_row + 64] = a1.w;
        *(float4*)&Bs[b_row][b_col]     = b0;
        *(float4*)&Bs[b_row + 8][b_col] = b1;
        __syncthreads();

#pragma unroll
        for (int kk = 0; kk < 16; kk++) {
            float ra[8], rb[8];
            *(float4*)&ra[0] = *(const float4*)&As[kk][ty * 8];
            *(float4*)&ra[4] = *(const float4*)&As[kk][ty * 8 + 4];
            *(float4*)&rb[0] = *(const float4*)&Bs[kk][tx * 8];
            *(float4*)&rb[4] = *(const float4*)&Bs[kk][tx * 8 + 4];
#pragma unroll
            for (int i = 0; i < 8; i++)
#pragma unroll
                for (int j = 0; j < 8; j++)
                    acc[i][j] += ra[i] * rb[j];
        }
        __syncthreads();
    }

#pragma unroll
    for (int i = 0; i < 8; i++) {
        float4 o0 = make_float4(acc[i][0], acc[i][1], acc[i][2], acc[i][3]);
        float4 o1 = make_float4(acc[i][4], acc[i][5], acc[i][6], acc[i][7]);
        size_t base = (size_t)(brow + ty * 8 + i) * N + bcol + tx * 8;
        *(float4*)&C[base]     = o0;
        *(float4*)&C[base + 4] = o1;
    }
}

// ---------------------------------------------------------------------------
// RoPE in-place on [L, nheads*128] buffer. grid (L, nheads), block 64.
// ---------------------------------------------------------------------------
__global__ void rope_kernel(float* __restrict__ buf, int stride)
{
    const int l = blockIdx.x;
    const int h = blockIdx.y;
    const int d = threadIdx.x;   // 0..63

    // inv_freq = 10000^{-(2d/128)}; angle = l * inv_freq  (double for phase accuracy)
    double inv_freq = exp(-9.210340371976184 * ((double)(2 * d) / 128.0)); // ln(1e4)
    double ang = (double)l * inv_freq;
    double sd, cd;
    sincos(ang, &sd, &cd);
    float c = (float)cd, s = (float)sd;

    float* p = buf + (size_t)l * stride + h * DHEAD;
    float x1 = p[d];
    float x2 = p[d + 64];
    p[d]      = x1 * c - x2 * s;
    p[d + 64] = x2 * c + x1 * s;
}

// ---------------------------------------------------------------------------
// lam[l][h] = sigmoid( x[l,:] . W_lam[:,h] + b_lam[h] ).  grid L, block 256.
// ---------------------------------------------------------------------------
__global__ void lam_kernel(const float* __restrict__ x,
                           const float* __restrict__ Wl,
                           const float* __restrict__ bl,
                           float* __restrict__ lam)
{
    __shared__ float part[256];
    const int l = blockIdx.x;
    const int t = threadIdx.x;
    const int h = t & 15;
    const int p = t >> 4;   // 16 partitions of K

    float s = 0.f;
#pragma unroll 4
    for (int j = 0; j < 128; j++) {
        int k = p * 128 + j;
        s += x[(size_t)l * D_MODEL + k] * Wl[(size_t)k * NHEADS + h];
    }
    part[t] = s;
    __syncthreads();
    if (t < NHEADS) {
        float tot = bl[t];
#pragma unroll
        for (int p2 = 0; p2 < 16; p2++) tot += part[p2 * 16 + t];
        lam[(size_t)l * NHEADS + t] = 1.f / (1.f + __expf(-tot));
    }
}

// ---------------------------------------------------------------------------
// Causal flash attention. grid (32 qblocks, 32 qheads), 256 threads.
// BQ=64 queries x BK=64 keys per iteration. Q/K smem tiles use a row-rotated
// layout (float4 group rotated by row) -> conflict-free stores AND reads.
// ---------------------------------------------------------------------------
#define ATT_SMEM_FLOATS (64 * 128 * 2 + 64 * 65)

__global__ __launch_bounds__(256) void attn_kernel(
    const float* __restrict__ q,   // [L, 4096]
    const float* __restrict__ k,   // [L, 2048]
    const float* __restrict__ v,   // [L, 2048]
    float* __restrict__ o)         // [32][L][128]
{
    extern __shared__ float sm[];
    float* Qs = sm;                 // [64][128] rotated
    float* KV = sm + 64 * 128;      // K rotated OR V row-major
    float* Ps = sm + 2 * 64 * 128;  // [64][65]

    const int qb  = blockIdx.x;
    const int qh  = blockIdx.y;
    const int kvh = qh >> 1;
    const int tid = threadIdx.x;
    const int tx  = tid & 15;
    const int ty  = tid >> 4;
    const float scale = 0.08838834764831843f;  // 1/sqrt(128)
    const float NEG = -1e30f;

    // ---- load Q tile (rotated, pre-scaled) ----
    {
        const float* src = q + (size_t)(qb * 64) * 4096 + qh * DHEAD;
#pragma unroll
        for (int u = 0; u < 8; u++) {
            int off = u * 1024 + tid * 4;
            int row = off >> 7, col = off & 127;
            float4 val = *(const float4*)&src[(size_t)row * 4096 + col];
            int c4 = ((((col >> 2) + row) & 31) << 2);
            float4 sv = make_float4(val.x * scale, val.y * scale,
                                    val.z * scale, val.w * scale);
            *(float4*)&Qs[row * 128 + c4] = sv;
        }
    }

    float m_i[4], l_i[4], acc[4][8];
#pragma unroll
    for (int i = 0; i < 4; i++) {
        m_i[i] = NEG; l_i[i] = 0.f;
#pragma unroll
        for (int j = 0; j < 8; j++) acc[i][j] = 0.f;
    }

    for (int kb = 0; kb <= qb; kb++) {
        __syncthreads();   // previous P@V done reading KV/Ps (and Qs visible on iter 0)

        // ---- load K tile (rotated) ----
        {
            const float* ksrc = k + (size_t)(kb * 64) * 2048 + kvh * DHEAD;
#pragma unroll
            for (int u = 0; u < 8; u++) {
                int off = u * 1024 + tid * 4;
                int row = off >> 7, col = off & 127;
                float4 val = *(const float4*)&ksrc[(size_t)row * 2048 + col];
                int c4 = ((((col >> 2) + row) & 31) << 2);
                *(float4*)&KV[row * 128 + c4] = val;
            }
        }
        __syncthreads();

        // ---- S = Q K^T  (4x4 per thread) ----
        float s[4][4];
#pragma unroll
        for (int i = 0; i < 4; i++)
#pragma unroll
            for (int j = 0; j < 4; j++) s[i][j] = 0.f;

#pragma unroll 8
        for (int kk = 0; kk < 128; kk += 4) {
            int g = kk >> 2;
            float4 qv[4], kv[4];
#pragma unroll
            for (int i = 0; i < 4; i++) {
                int r = ty * 4 + i;
                qv[i] = *(const float4*)&Qs[r * 128 + (((g + r) & 31) << 2)];
            }
#pragma unroll
            for (int j = 0; j < 4; j++) {
                int r = tx * 4 + j;
                kv[j] = *(const float4*)&KV[r * 128 + (((g + r) & 31) << 2)];
            }
#pragma unroll
            for (int i = 0; i < 4; i++)
#pragma unroll
                for (int j = 0; j < 4; j++)
                    s[i][j] += qv[i].x * kv[j].x + qv[i].y * kv[j].y
                             + qv[i].z * kv[j].z + qv[i].w * kv[j].w;
        }

        // ---- causal mask (only on diagonal block) ----
        if (kb == qb) {
#pragma unroll
            for (int i = 0; i < 4; i++)
#pragma unroll
                for (int j = 0; j < 4; j++)
                    if (tx * 4 + j > ty * 4 + i) s[i][j] = NEG;
        }

        // ---- online softmax (row groups = 16 tx lanes, warp-contained) ----
#pragma unroll
        for (int i = 0; i < 4; i++) {
            float mx = fmaxf(fmaxf(s[i][0], s[i][1]), fmaxf(s[i][2], s[i][3]));
            mx = fmaxf(mx, __shfl_xor_sync(0xffffffffu, mx, 1));
            mx = fmaxf(mx, __shfl_xor_sync(0xffffffffu, mx, 2));
            mx = fmaxf(mx, __shfl_xor_sync(0xffffffffu, mx, 4));
            mx = fmaxf(mx, __shfl_xor_sync(0xffffffffu, mx, 8));
            float mnew  = fmaxf(m_i[i], mx);
            float alpha = __expf(m_i[i] - mnew);
            m_i[i] = mnew;
            float rs = 0.f;
#pragma unroll
            for (int j = 0; j < 4; j++) {
                float pj = __expf(s[i][j] - mnew);
                s[i][j] = pj;
                rs += pj;
            }
            rs += __shfl_xor_sync(0xffffffffu, rs, 1);
            rs += __shfl_xor_sync(0xffffffffu, rs, 2);
            rs += __shfl_xor_sync(0xffffffffu, rs, 4);
            rs += __shfl_xor_sync(0xffffffffu, rs, 8);
            l_i[i] = l_i[i] * alpha + rs;
#pragma unroll
            for (int j2 = 0; j2 < 8; j2++) acc[i][j2] *= alpha;
#pragma unroll
            for (int j = 0; j < 4; j++)
                Ps[(ty * 4 + i) * 65 + tx * 4 + j] = s[i][j];
        }
        __syncthreads();   // S reads of KV done, Ps visible

        // ---- load V tile (row-major) into KV ----
        {
            const float* vsrc = v + (size_t)(kb * 64) * 2048 + kvh * DHEAD;
#pragma unroll
            for (int u = 0; u < 8; u++) {
                int off = u * 1024 + tid * 4;
                int row = off >> 7, col = off & 127;
                *(float4*)&KV[row * 128 + col] =
                    *(const float4*)&vsrc[(size_t)row * 2048 + col];
            }
        }
        __syncthreads();

        // ---- acc += P @ V  (4 rows x 8 cols per thread) ----
#pragma unroll 8
        for (int kk = 0; kk < 64; kk++) {
            float pr[4];
#pragma unroll
            for (int i = 0; i < 4; i++) pr[i] = Ps[(ty * 4 + i) * 65 + kk];
            float4 v0 = *(const float4*)&KV[kk * 128 + tx * 8];
            float4 v1 = *(const float4*)&KV[kk * 128 + tx * 8 + 4];
#pragma unroll
            for (int i = 0; i < 4; i++) {
                acc[i][0] += pr[i] * v0.x;  acc[i][1] += pr[i] * v0.y;
                acc[i][2] += pr[i] * v0.z;  acc[i][3] += pr[i] * v0.w;
                acc[i][4] += pr[i] * v1.x;  acc[i][5] += pr[i] * v1.y;
                acc[i][6] += pr[i] * v1.z;  acc[i][7] += pr[i] * v1.w;
            }
        }
    }

    // ---- normalize and write ----
#pragma unroll
    for (int i = 0; i < 4; i++) {
        float inv = 1.f / l_i[i];
        float4 o0 = make_float4(acc[i][0] * inv, acc[i][1] * inv,
                                acc[i][2] * inv, acc[i][3] * inv);
        float4 o1 = make_float4(acc[i][4] * inv, acc[i][5] * inv,
                                acc[i][6] * inv, acc[i][7] * inv);
        size_t base = ((size_t)qh * L_SEQ + qb * 64 + ty * 4 + i) * DHEAD + tx * 8;
        *(float4*)&o[base]     = o0;
        *(float4*)&o[base + 4] = o1;
    }
}

// ---------------------------------------------------------------------------
// combine: out[l, h*128+d] = attn1 - lam[l,h] * attn2
// ---------------------------------------------------------------------------
__global__ void combine_kernel(const float* __restrict__ attn,
                               const float* __restrict__ lam,
                               float* __restrict__ out)
{
    int idx = blockIdx.x * 256 + threadIdx.x;   // over L*2048
    int l = idx >> 11;
    int c = idx & 2047;
    int h = c >> 7;
    int d = c & 127;
    float a1 = attn[((size_t)(2 * h)     * L_SEQ + l) * DHEAD + d];
    float a2 = attn[((size_t)(2 * h + 1) * L_SEQ + l) * DHEAD + d];
    out[idx] = a1 - lam[(size_t)l * NHEADS + h] * a2;
}

// ---------------------------------------------------------------------------
// kernel_launch
// inputs: 0=x 1=W_DKV 2=W_UK 3=W_UV 4=W_DQ 5=W_UQ 6=W_lam 7=b_lam 8=W_out
// ---------------------------------------------------------------------------
extern "C" void kernel_launch(void* const* d_in, const int* in_sizes, int n_in,
                              void* d_out, int out_size)
{
    const float* x     = (const float*)d_in[0];
    const float* W_DKV = (const float*)d_in[1];
    const float* W_UK  = (const float*)d_in[2];
    const float* W_UV  = (const float*)d_in[3];
    const float* W_DQ  = (const float*)d_in[4];
    const float* W_UQ  = (const float*)d_in[5];
    const float* W_lam = (const float*)d_in[6];
    const float* b_lam = (const float*)d_in[7];
    const float* W_out = (const float*)d_in[8];
    float* out = (float*)d_out;

    float *ckv, *kbuf, *vbuf, *cq, *qbuf, *attn, *lam, *comb;
    cudaGetSymbolAddress((void**)&ckv,  g_ckv);
    cudaGetSymbolAddress((void**)&kbuf, g_k);
    cudaGetSymbolAddress((void**)&vbuf, g_v);
    cudaGetSymbolAddress((void**)&cq,   g_cq);
    cudaGetSymbolAddress((void**)&qbuf, g_q);
    cudaGetSymbolAddress((void**)&attn, g_attn);
    cudaGetSymbolAddress((void**)&lam,  g_lam);
    cudaGetSymbolAddress((void**)&comb, g_comb);

    // projections
    sgemm_kernel<<<dim3(DC / 128,      L_SEQ / 128), 256>>>(x,    W_DKV, ckv,  L_SEQ, DC,      D_MODEL);
    sgemm_kernel<<<dim3(D_MODEL / 128, L_SEQ / 128), 256>>>(ckv,  W_UK,  kbuf, L_SEQ, D_MODEL, DC);
    sgemm_kernel<<<dim3(D_MODEL / 128, L_SEQ / 128), 256>>>(ckv,  W_UV,  vbuf, L_SEQ, D_MODEL, DC);
    sgemm_kernel<<<dim3(DCQ / 128,     L_SEQ / 128), 256>>>(x,    W_DQ,  cq,   L_SEQ, DCQ,     D_MODEL);
    sgemm_kernel<<<dim3(4096 / 128,    L_SEQ / 128), 256>>>(cq,   W_UQ,  qbuf, L_SEQ, 4096,    DCQ);

    // RoPE
    rope_kernel<<<dim3(L_SEQ, QHEADS), 64>>>(qbuf, 2 * D_MODEL);
    rope_kernel<<<dim3(L_SEQ, NHEADS), 64>>>(kbuf, D_MODEL);

    // gate
    lam_kernel<<<L_SEQ, 256>>>(x, W_lam, b_lam, lam);

    // attention
    int smem = ATT_SMEM_FLOATS * (int)sizeof(float);
    cudaFuncSetAttribute(attn_kernel, cudaFuncAttributeMaxDynamicSharedMemorySize, smem);
    attn_kernel<<<dim3(L_SEQ / 64, QHEADS), 256, smem>>>(qbuf, kbuf, vbuf, attn);

    // differential combine
    combine_kernel<<<(L_SEQ * D_MODEL) / 256, 256>>>(attn, lam, comb);

    // output projection
    sgemm_kernel<<<dim3(D_MODEL / 128, L_SEQ / 128), 256>>>(comb, W_out, out, L_SEQ, D_MODEL, D_MODEL);
}

// round 6
// speedup vs baseline: 1.3873x; 1.3873x over previous
#include <cuda_runtime.h>
#include <cuda_bf16.h>
#include <math.h>
#include <stdint.h>

#define L_SEQ   2048
#define D_MODEL 2048
#define NHEADS  16
#define DHEAD   128
#define DC      512
#define DCQ     1024
#define QHEADS  32   // 2 * NHEADS

// ---------------------------------------------------------------------------
// Scratch (static device globals -- no runtime allocation allowed)
// ---------------------------------------------------------------------------
__device__ float g_ckv [L_SEQ * DC];
__device__ float g_k   [L_SEQ * D_MODEL];
__device__ float g_v   [L_SEQ * D_MODEL];
__device__ float g_cq  [L_SEQ * DCQ];
__device__ float g_q   [L_SEQ * 2 * D_MODEL];
__device__ float g_attn[QHEADS * L_SEQ * DHEAD];
__device__ float g_lam [L_SEQ * NHEADS];
__device__ float g_comb[L_SEQ * D_MODEL];

// ---------------------------------------------------------------------------
// Helpers: smem address, bf16 hi/lo split, ldmatrix, mma.sync (sm_80 baseline
// features -- compile on plain sm_103 target, unlike tcgen05/*a* features)
// ---------------------------------------------------------------------------
__device__ __forceinline__ uint32_t smem_u32(const void* p) {
    uint32_t r;
    asm("{ .reg .u64 t; cvta.to.shared.u64 t, %1; cvt.u32.u64 %0, t; }"
        : "=r"(r) : "l"(p));
    return r;
}

__device__ __forceinline__ void split_bf(float v, uint16_t& h, uint16_t& l) {
    __nv_bfloat16 hb = __float2bfloat16_rn(v);
    float hf = __bfloat162float(hb);
    __nv_bfloat16 lb = __float2bfloat16_rn(v - hf);
    h = *(uint16_t*)&hb;
    l = *(uint16_t*)&lb;
}

__device__ __forceinline__ void ldsm_x4(uint32_t* r, uint32_t addr) {
    asm volatile("ldmatrix.sync.aligned.m8n8.x4.shared.b16 {%0,%1,%2,%3}, [%4];"
                 : "=r"(r[0]), "=r"(r[1]), "=r"(r[2]), "=r"(r[3]) : "r"(addr));
}
__device__ __forceinline__ void ldsm_x2_t(uint32_t* r, uint32_t addr) {
    asm volatile("ldmatrix.sync.aligned.m8n8.x2.trans.shared.b16 {%0,%1}, [%2];"
                 : "=r"(r[0]), "=r"(r[1]) : "r"(addr));
}
__device__ __forceinline__ void mma_bf16(float* d, const uint32_t* a, const uint32_t* b) {
    asm volatile(
        "mma.sync.aligned.m16n8k16.row.col.f32.bf16.bf16.f32 "
        "{%0,%1,%2,%3}, {%4,%5,%6,%7}, {%8,%9}, {%0,%1,%2,%3};"
        : "+f"(d[0]), "+f"(d[1]), "+f"(d[2]), "+f"(d[3])
        : "r"(a[0]), "r"(a[1]), "r"(a[2]), "r"(a[3]), "r"(b[0]), "r"(b[1]));
}

// ---------------------------------------------------------------------------
// TC GEMM: C[M,N] = A[M,K] @ B[K,N] fp32, via bf16 hi/lo 3-term split on
// warp-level tensor cores (mma.sync). 128x128 tile, BK=32, 256 threads
// (8 warps, 2x4; each warp 64x32). Fully synchronous -- no mbarriers.
// Requires M%128==0, N%128==0, K%32==0 (true for every call here).
// ---------------------------------------------------------------------------
#define A_ROW_B 80    // 32 bf16 = 64B + 16B pad (ldmatrix conflict-free)
#define B_ROW_B 272   // 128 bf16 = 256B + 16B pad
#define SM_AHI  0
#define SM_ALO  (128 * A_ROW_B)            // 10240
#define SM_BHI  (2 * 128 * A_ROW_B)        // 20480
#define SM_BLO  (SM_BHI + 32 * B_ROW_B)    // 29184
#define SM_TOT  (SM_BLO + 32 * B_ROW_B)    // 37888

__global__ __launch_bounds__(256, 2)
void tc_gemm(const float* __restrict__ A, const float* __restrict__ B,
             float* __restrict__ C, int M, int N, int K)
{
    __shared__ __align__(16) char sm[SM_TOT];

    const int tid  = threadIdx.x;
    const int wid  = tid >> 5;
    const int lane = tid & 31;
    const int wr   = wid >> 2;       // 0..1  (warp row: 64 rows each)
    const int wc   = wid & 3;        // 0..3  (warp col: 32 cols each)
    const int brow = blockIdx.y * 128;
    const int bcol = blockIdx.x * 128;

    const uint32_t sbase = smem_u32(sm);

    float acc[4][4][4];
#pragma unroll
    for (int i = 0; i < 4; i++)
#pragma unroll
        for (int j = 0; j < 4; j++)
#pragma unroll
            for (int t = 0; t < 4; t++) acc[i][j][t] = 0.f;

    // precomputed ldmatrix lane addresses
    // A (.x4): lanes 0-15 -> rows 0-15 @k, lanes 16-31 -> rows 0-15 @k+8
    const uint32_t a_lane_off = (uint32_t)((lane & 15) * A_ROW_B + ((lane >> 4) << 3) * 2);
    // B (.x2.trans): lanes 0-15 -> k rows 0-15 (16-31 mirrored, ignored)
    const uint32_t b_lane_off = (uint32_t)((lane & 15) * B_ROW_B);

    const int nIter = K >> 5;
    for (int it = 0; it < nIter; it++) {
        const int k0 = it << 5;

        // ---- load fp32 tiles, split to bf16 hi/lo, store smem ----
#pragma unroll
        for (int u = 0; u < 4; u++) {
            int idx = u * 256 + tid;                // 0..1023
            {   // A: [128 rows][32 k]
                int row = idx >> 3, c4 = (idx & 7) << 2;
                const float4 a = *(const float4*)&A[(size_t)(brow + row) * K + k0 + c4];
                uint16_t h0,h1,h2,h3,l0,l1,l2,l3;
                split_bf(a.x,h0,l0); split_bf(a.y,h1,l1);
                split_bf(a.z,h2,l2); split_bf(a.w,h3,l3);
                uint32_t off = (uint32_t)(row * A_ROW_B + c4 * 2);
                *(uint2*)(sm + SM_AHI + off) =
                    make_uint2((uint32_t)h0 | ((uint32_t)h1 << 16),
                               (uint32_t)h2 | ((uint32_t)h3 << 16));
                *(uint2*)(sm + SM_ALO + off) =
                    make_uint2((uint32_t)l0 | ((uint32_t)l1 << 16),
                               (uint32_t)l2 | ((uint32_t)l3 << 16));
            }
            {   // B: [32 k][128 n]
                int kk = idx >> 5, n4 = (idx & 31) << 2;
                const float4 b = *(const float4*)&B[(size_t)(k0 + kk) * N + bcol + n4];
                uint16_t h0,h1,h2,h3,l0,l1,l2,l3;
                split_bf(b.x,h0,l0); split_bf(b.y,h1,l1);
                split_bf(b.z,h2,l2); split_bf(b.w,h3,l3);
                uint32_t off = (uint32_t)(kk * B_ROW_B + n4 * 2);
                *(uint2*)(sm + SM_BHI + off) =
                    make_uint2((uint32_t)h0 | ((uint32_t)h1 << 16),
                               (uint32_t)h2 | ((uint32_t)h3 << 16));
                *(uint2*)(sm + SM_BLO + off) =
                    make_uint2((uint32_t)l0 | ((uint32_t)l1 << 16),
                               (uint32_t)l2 | ((uint32_t)l3 << 16));
            }
        }
        __syncthreads();

        // ---- tensor phase: 2 k16-steps x 4 m-frags x 4 n-frags x 3 terms ----
#pragma unroll
        for (int ks = 0; ks < 2; ks++) {
            const uint32_t kb16 = (uint32_t)(ks * 16);
            uint32_t bhi[4][2], blo[4][2];
#pragma unroll
            for (int fn = 0; fn < 4; fn++) {
                uint32_t nb = (uint32_t)((wc * 32 + fn * 8) * 2);
                uint32_t ba = sbase + kb16 * B_ROW_B + b_lane_off + nb;
                ldsm_x2_t(bhi[fn], ba + SM_BHI);
                ldsm_x2_t(blo[fn], ba + SM_BLO);
            }
#pragma unroll
            for (int fm = 0; fm < 4; fm++) {
                uint32_t row0 = (uint32_t)(wr * 64 + fm * 16);
                uint32_t aa = sbase + row0 * A_ROW_B + kb16 * 2 + a_lane_off;
                uint32_t ahi[4], alo[4];
                ldsm_x4(ahi, aa + SM_AHI);
                ldsm_x4(alo, aa + SM_ALO);
#pragma unroll
                for (int fn = 0; fn < 4; fn++) {
                    mma_bf16(acc[fm][fn], ahi, bhi[fn]);
                    mma_bf16(acc[fm][fn], ahi, blo[fn]);
                    mma_bf16(acc[fm][fn], alo, bhi[fn]);
                }
            }
        }
        __syncthreads();
    }

    // ---- epilogue: write fragments (float2 per row-half) ----
#pragma unroll
    for (int fm = 0; fm < 4; fm++) {
#pragma unroll
        for (int fn = 0; fn < 4; fn++) {
            int r0 = brow + wr * 64 + fm * 16 + (lane >> 2);
            int c0 = bcol + wc * 32 + fn * 8 + (lane & 3) * 2;
            *(float2*)&C[(size_t)r0 * N + c0] =
                make_float2(acc[fm][fn][0], acc[fm][fn][1]);
            *(float2*)&C[(size_t)(r0 + 8) * N + c0] =
                make_float2(acc[fm][fn][2], acc[fm][fn][3]);
        }
    }
}

// ---------------------------------------------------------------------------
// RoPE in-place (fp32; matches reference's fp32 angle computation)
// ---------------------------------------------------------------------------
__global__ void rope_kernel(float* __restrict__ buf, int stride)
{
    const int l = blockIdx.x;
    const int h = blockIdx.y;
    const int d = threadIdx.x;   // 0..63

    float inv_freq = exp2f(-(float)d * (13.287712379549449f / 64.f));
    float ang = (float)l * inv_freq;
    float s, c;
    sincosf(ang, &s, &c);

    float* p = buf + (size_t)l * stride + h * DHEAD;
    float x1 = p[d];
    float x2 = p[d + 64];
    p[d]      = x1 * c - x2 * s;
    p[d + 64] = x2 * c + x1 * s;
}

// ---------------------------------------------------------------------------
// lam[l][h] = sigmoid( x[l,:] . W_lam[:,h] + b_lam[h] )
// ---------------------------------------------------------------------------
__global__ void lam_kernel(const float* __restrict__ x,
                           const float* __restrict__ Wl,
                           const float* __restrict__ bl,
                           float* __restrict__ lam)
{
    __shared__ float part[256];
    const int l = blockIdx.x;
    const int t = threadIdx.x;
    const int h = t & 15;
    const int p = t >> 4;

    float s = 0.f;
#pragma unroll 4
    for (int j = 0; j < 128; j++) {
        int k = p * 128 + j;
        s += x[(size_t)l * D_MODEL + k] * Wl[(size_t)k * NHEADS + h];
    }
    part[t] = s;
    __syncthreads();
    if (t < NHEADS) {
        float tot = bl[t];
#pragma unroll
        for (int p2 = 0; p2 < 16; p2++) tot += part[p2 * 16 + t];
        lam[(size_t)l * NHEADS + t] = 1.f / (1.f + __expf(-tot));
    }
}

// ---------------------------------------------------------------------------
// Causal flash attention (unchanged from passing R3 kernel)
// ---------------------------------------------------------------------------
#define ATT_SMEM_FLOATS (64 * 128 * 2 + 64 * 65)

__global__ __launch_bounds__(256) void attn_kernel(
    const float* __restrict__ q,
    const float* __restrict__ k,
    const float* __restrict__ v,
    float* __restrict__ o)
{
    extern __shared__ float sm[];
    float* Qs = sm;
    float* KV = sm + 64 * 128;
    float* Ps = sm + 2 * 64 * 128;

    const int qb  = blockIdx.x;
    const int qh  = blockIdx.y;
    const int kvh = qh >> 1;
    const int tid = threadIdx.x;
    const int tx  = tid & 15;
    const int ty  = tid >> 4;
    const float scale = 0.08838834764831843f;
    const float NEG = -1e30f;

    {
        const float* src = q + (size_t)(qb * 64) * 4096 + qh * DHEAD;
#pragma unroll
        for (int u = 0; u < 8; u++) {
            int off = u * 1024 + tid * 4;
            int row = off >> 7, col = off & 127;
            float4 val = *(const float4*)&src[(size_t)row * 4096 + col];
            int c4 = ((((col >> 2) + row) & 31) << 2);
            float4 sv = make_float4(val.x * scale, val.y * scale,
                                    val.z * scale, val.w * scale);
            *(float4*)&Qs[row * 128 + c4] = sv;
        }
    }

    float m_i[4], l_i[4], acc[4][8];
#pragma unroll
    for (int i = 0; i < 4; i++) {
        m_i[i] = NEG; l_i[i] = 0.f;
#pragma unroll
        for (int j = 0; j < 8; j++) acc[i][j] = 0.f;
    }

    for (int kb = 0; kb <= qb; kb++) {
        __syncthreads();

        {
            const float* ksrc = k + (size_t)(kb * 64) * 2048 + kvh * DHEAD;
#pragma unroll
            for (int u = 0; u < 8; u++) {
                int off = u * 1024 + tid * 4;
                int row = off >> 7, col = off & 127;
                float4 val = *(const float4*)&ksrc[(size_t)row * 2048 + col];
                int c4 = ((((col >> 2) + row) & 31) << 2);
                *(float4*)&KV[row * 128 + c4] = val;
            }
        }
        __syncthreads();

        float s[4][4];
#pragma unroll
        for (int i = 0; i < 4; i++)
#pragma unroll
            for (int j = 0; j < 4; j++) s[i][j] = 0.f;

#pragma unroll 8
        for (int kk = 0; kk < 128; kk += 4) {
            int g = kk >> 2;
            float4 qv[4], kv[4];
#pragma unroll
            for (int i = 0; i < 4; i++) {
                int r = ty * 4 + i;
                qv[i] = *(const float4*)&Qs[r * 128 + (((g + r) & 31) << 2)];
            }
#pragma unroll
            for (int j = 0; j < 4; j++) {
                int r = tx * 4 + j;
                kv[j] = *(const float4*)&KV[r * 128 + (((g + r) & 31) << 2)];
            }
#pragma unroll
            for (int i = 0; i < 4; i++)
#pragma unroll
                for (int j = 0; j < 4; j++)
                    s[i][j] += qv[i].x * kv[j].x + qv[i].y * kv[j].y
                             + qv[i].z * kv[j].z + qv[i].w * kv[j].w;
        }

        if (kb == qb) {
#pragma unroll
            for (int i = 0; i < 4; i++)
#pragma unroll
                for (int j = 0; j < 4; j++)
                    if (tx * 4 + j > ty * 4 + i) s[i][j] = NEG;
        }

#pragma unroll
        for (int i = 0; i < 4; i++) {
            float mx = fmaxf(fmaxf(s[i][0], s[i][1]), fmaxf(s[i][2], s[i][3]));
            mx = fmaxf(mx, __shfl_xor_sync(0xffffffffu, mx, 1));
            mx = fmaxf(mx, __shfl_xor_sync(0xffffffffu, mx, 2));
            mx = fmaxf(mx, __shfl_xor_sync(0xffffffffu, mx, 4));
            mx = fmaxf(mx, __shfl_xor_sync(0xffffffffu, mx, 8));
            float mnew  = fmaxf(m_i[i], mx);
            float alpha = __expf(m_i[i] - mnew);
            m_i[i] = mnew;
            float rs = 0.f;
#pragma unroll
            for (int j = 0; j < 4; j++) {
                float pj = __expf(s[i][j] - mnew);
                s[i][j] = pj;
                rs += pj;
            }
            rs += __shfl_xor_sync(0xffffffffu, rs, 1);
            rs += __shfl_xor_sync(0xffffffffu, rs, 2);
            rs += __shfl_xor_sync(0xffffffffu, rs, 4);
            rs += __shfl_xor_sync(0xffffffffu, rs, 8);
            l_i[i] = l_i[i] * alpha + rs;
#pragma unroll
            for (int j2 = 0; j2 < 8; j2++) acc[i][j2] *= alpha;
#pragma unroll
            for (int j = 0; j < 4; j++)
                Ps[(ty * 4 + i) * 65 + tx * 4 + j] = s[i][j];
        }
        __syncthreads();

        {
            const float* vsrc = v + (size_t)(kb * 64) * 2048 + kvh * DHEAD;
#pragma unroll
            for (int u = 0; u < 8; u++) {
                int off = u * 1024 + tid * 4;
                int row = off >> 7, col = off & 127;
                *(float4*)&KV[row * 128 + col] =
                    *(const float4*)&vsrc[(size_t)row * 2048 + col];
            }
        }
        __syncthreads();

#pragma unroll 8
        for (int kk = 0; kk < 64; kk++) {
            float pr[4];
#pragma unroll
            for (int i = 0; i < 4; i++) pr[i] = Ps[(ty * 4 + i) * 65 + kk];
            float4 v0 = *(const float4*)&KV[kk * 128 + tx * 8];
            float4 v1 = *(const float4*)&KV[kk * 128 + tx * 8 + 4];
#pragma unroll
            for (int i = 0; i < 4; i++) {
                acc[i][0] += pr[i] * v0.x;  acc[i][1] += pr[i] * v0.y;
                acc[i][2] += pr[i] * v0.z;  acc[i][3] += pr[i] * v0.w;
                acc[i][4] += pr[i] * v1.x;  acc[i][5] += pr[i] * v1.y;
                acc[i][6] += pr[i] * v1.z;  acc[i][7] += pr[i] * v1.w;
            }
        }
    }

#pragma unroll
    for (int i = 0; i < 4; i++) {
        float inv = 1.f / l_i[i];
        float4 o0 = make_float4(acc[i][0] * inv, acc[i][1] * inv,
                                acc[i][2] * inv, acc[i][3] * inv);
        float4 o1 = make_float4(acc[i][4] * inv, acc[i][5] * inv,
                                acc[i][6] * inv, acc[i][7] * inv);
        size_t base = ((size_t)qh * L_SEQ + qb * 64 + ty * 4 + i) * DHEAD + tx * 8;
        *(float4*)&o[base]     = o0;
        *(float4*)&o[base + 4] = o1;
    }
}

// ---------------------------------------------------------------------------
// combine: out[l, h*128+d] = attn1 - lam[l,h] * attn2
// ---------------------------------------------------------------------------
__global__ void combine_kernel(const float* __restrict__ attn,
                               const float* __restrict__ lam,
                               float* __restrict__ out)
{
    int idx = blockIdx.x * 256 + threadIdx.x;
    int l = idx >> 11;
    int c = idx & 2047;
    int h = c >> 7;
    int d = c & 127;
    float a1 = attn[((size_t)(2 * h)     * L_SEQ + l) * DHEAD + d];
    float a2 = attn[((size_t)(2 * h + 1) * L_SEQ + l) * DHEAD + d];
    out[idx] = a1 - lam[(size_t)l * NHEADS + h] * a2;
}

// ---------------------------------------------------------------------------
// kernel_launch
// inputs: 0=x 1=W_DKV 2=W_UK 3=W_UV 4=W_DQ 5=W_UQ 6=W_lam 7=b_lam 8=W_out
// ---------------------------------------------------------------------------
extern "C" void kernel_launch(void* const* d_in, const int* in_sizes, int n_in,
                              void* d_out, int out_size)
{
    const float* x     = (const float*)d_in[0];
    const float* W_DKV = (const float*)d_in[1];
    const float* W_UK  = (const float*)d_in[2];
    const float* W_UV  = (const float*)d_in[3];
    const float* W_DQ  = (const float*)d_in[4];
    const float* W_UQ  = (const float*)d_in[5];
    const float* W_lam = (const float*)d_in[6];
    const float* b_lam = (const float*)d_in[7];
    const float* W_out = (const float*)d_in[8];
    float* out = (float*)d_out;

    float *ckv, *kbuf, *vbuf, *cq, *qbuf, *attn, *lam, *comb;
    cudaGetSymbolAddress((void**)&ckv,  g_ckv);
    cudaGetSymbolAddress((void**)&kbuf, g_k);
    cudaGetSymbolAddress((void**)&vbuf, g_v);
    cudaGetSymbolAddress((void**)&cq,   g_cq);
    cudaGetSymbolAddress((void**)&qbuf, g_q);
    cudaGetSymbolAddress((void**)&attn, g_attn);
    cudaGetSymbolAddress((void**)&lam,  g_lam);
    cudaGetSymbolAddress((void**)&comb, g_comb);

    // projections (warp-level bf16 3-term tensor-core GEMM)
    tc_gemm<<<dim3(DC / 128,      L_SEQ / 128), 256>>>(x,   W_DKV, ckv,  L_SEQ, DC,      D_MODEL);
    tc_gemm<<<dim3(D_MODEL / 128, L_SEQ / 128), 256>>>(ckv, W_UK,  kbuf, L_SEQ, D_MODEL, DC);
    tc_gemm<<<dim3(D_MODEL / 128, L_SEQ / 128), 256>>>(ckv, W_UV,  vbuf, L_SEQ, D_MODEL, DC);
    tc_gemm<<<dim3(DCQ / 128,     L_SEQ / 128), 256>>>(x,   W_DQ,  cq,   L_SEQ, DCQ,     D_MODEL);
    tc_gemm<<<dim3(4096 / 128,    L_SEQ / 128), 256>>>(cq,  W_UQ,  qbuf, L_SEQ, 4096,    DCQ);

    // RoPE
    rope_kernel<<<dim3(L_SEQ, QHEADS), 64>>>(qbuf, 2 * D_MODEL);
    rope_kernel<<<dim3(L_SEQ, NHEADS), 64>>>(kbuf, D_MODEL);

    // gate
    lam_kernel<<<L_SEQ, 256>>>(x, W_lam, b_lam, lam);

    // attention
    int smem = ATT_SMEM_FLOATS * (int)sizeof(float);
    cudaFuncSetAttribute(attn_kernel, cudaFuncAttributeMaxDynamicSharedMemorySize, smem);
    attn_kernel<<<dim3(L_SEQ / 64, QHEADS), 256, smem>>>(qbuf, kbuf, vbuf, attn);

    // differential combine
    combine_kernel<<<(L_SEQ * D_MODEL) / 256, 256>>>(attn, lam, comb);

    // output projection
    tc_gemm<<<dim3(D_MODEL / 128, L_SEQ / 128), 256>>>(comb, W_out, out, L_SEQ, D_MODEL, D_MODEL);
}

// round 7
// speedup vs baseline: 3.2070x; 2.3116x over previous
#include <cuda_runtime.h>
#include <cuda_bf16.h>
#include <math.h>
#include <stdint.h>

#define L_SEQ   2048
#define D_MODEL 2048
#define NHEADS  16
#define DHEAD   128
#define DC      512
#define DCQ     1024
#define QHEADS  32   // 2 * NHEADS

// ---------------------------------------------------------------------------
// Scratch (static device globals -- no runtime allocation allowed)
// ---------------------------------------------------------------------------
__device__ float g_ckv [L_SEQ * DC];
__device__ float g_k   [L_SEQ * D_MODEL];
__device__ float g_v   [L_SEQ * D_MODEL];
__device__ float g_cq  [L_SEQ * DCQ];
__device__ float g_q   [L_SEQ * 2 * D_MODEL];
__device__ float g_attn[QHEADS * L_SEQ * DHEAD];
__device__ float g_lam [L_SEQ * NHEADS];
__device__ float g_comb[L_SEQ * D_MODEL];

// ---------------------------------------------------------------------------
// Helpers (sm_80-baseline features: compile on plain sm_103 target)
// ---------------------------------------------------------------------------
__device__ __forceinline__ uint32_t smem_u32(const void* p) {
    uint32_t r;
    asm("{ .reg .u64 t; cvta.to.shared.u64 t, %1; cvt.u32.u64 %0, t; }"
        : "=r"(r) : "l"(p));
    return r;
}

__device__ __forceinline__ void split_bf(float v, uint16_t& h, uint16_t& l) {
    __nv_bfloat16 hb = __float2bfloat16_rn(v);
    float hf = __bfloat162float(hb);
    __nv_bfloat16 lb = __float2bfloat16_rn(v - hf);
    h = *(uint16_t*)&hb;
    l = *(uint16_t*)&lb;
}
// split two floats -> packed bf16x2 hi and lo words
__device__ __forceinline__ void split2(float a, float b, uint32_t& hp, uint32_t& lp) {
    uint16_t ha, la, hb, lb;
    split_bf(a, ha, la);
    split_bf(b, hb, lb);
    hp = (uint32_t)ha | ((uint32_t)hb << 16);
    lp = (uint32_t)la | ((uint32_t)lb << 16);
}

__device__ __forceinline__ void ldsm_x4(uint32_t* r, uint32_t addr) {
    asm volatile("ldmatrix.sync.aligned.m8n8.x4.shared.b16 {%0,%1,%2,%3}, [%4];"
                 : "=r"(r[0]), "=r"(r[1]), "=r"(r[2]), "=r"(r[3]) : "r"(addr));
}
__device__ __forceinline__ void ldsm_x2_t(uint32_t* r, uint32_t addr) {
    asm volatile("ldmatrix.sync.aligned.m8n8.x2.trans.shared.b16 {%0,%1}, [%2];"
                 : "=r"(r[0]), "=r"(r[1]) : "r"(addr));
}
__device__ __forceinline__ void mma_bf16(float* d, const uint32_t* a, const uint32_t* b) {
    asm volatile(
        "mma.sync.aligned.m16n8k16.row.col.f32.bf16.bf16.f32 "
        "{%0,%1,%2,%3}, {%4,%5,%6,%7}, {%8,%9}, {%0,%1,%2,%3};"
        : "+f"(d[0]), "+f"(d[1]), "+f"(d[2]), "+f"(d[3])
        : "r"(a[0]), "r"(a[1]), "r"(a[2]), "r"(a[3]), "r"(b[0]), "r"(b[1]));
}

// ---------------------------------------------------------------------------
// TC GEMM (unchanged from R5 -- validated): C = A@B fp32 via bf16 3-term split
// ---------------------------------------------------------------------------
#define A_ROW_B 80
#define B_ROW_B 272
#define SM_AHI  0
#define SM_ALO  (128 * A_ROW_B)
#define SM_BHI  (2 * 128 * A_ROW_B)
#define SM_BLO  (SM_BHI + 32 * B_ROW_B)
#define SM_TOT  (SM_BLO + 32 * B_ROW_B)

__global__ __launch_bounds__(256, 2)
void tc_gemm(const float* __restrict__ A, const float* __restrict__ B,
             float* __restrict__ C, int M, int N, int K)
{
    __shared__ __align__(16) char sm[SM_TOT];

    const int tid  = threadIdx.x;
    const int wid  = tid >> 5;
    const int lane = tid & 31;
    const int wr   = wid >> 2;
    const int wc   = wid & 3;
    const int brow = blockIdx.y * 128;
    const int bcol = blockIdx.x * 128;

    const uint32_t sbase = smem_u32(sm);

    float acc[4][4][4];
#pragma unroll
    for (int i = 0; i < 4; i++)
#pragma unroll
        for (int j = 0; j < 4; j++)
#pragma unroll
            for (int t = 0; t < 4; t++) acc[i][j][t] = 0.f;

    const uint32_t a_lane_off = (uint32_t)((lane & 15) * A_ROW_B + ((lane >> 4) << 3) * 2);
    const uint32_t b_lane_off = (uint32_t)((lane & 15) * B_ROW_B);

    const int nIter = K >> 5;
    for (int it = 0; it < nIter; it++) {
        const int k0 = it << 5;
#pragma unroll
        for (int u = 0; u < 4; u++) {
            int idx = u * 256 + tid;
            {
                int row = idx >> 3, c4 = (idx & 7) << 2;
                const float4 a = *(const float4*)&A[(size_t)(brow + row) * K + k0 + c4];
                uint32_t h0, l0, h1, l1;
                split2(a.x, a.y, h0, l0);
                split2(a.z, a.w, h1, l1);
                uint32_t off = (uint32_t)(row * A_ROW_B + c4 * 2);
                *(uint2*)(sm + SM_AHI + off) = make_uint2(h0, h1);
                *(uint2*)(sm + SM_ALO + off) = make_uint2(l0, l1);
            }
            {
                int kk = idx >> 5, n4 = (idx & 31) << 2;
                const float4 b = *(const float4*)&B[(size_t)(k0 + kk) * N + bcol + n4];
                uint32_t h0, l0, h1, l1;
                split2(b.x, b.y, h0, l0);
                split2(b.z, b.w, h1, l1);
                uint32_t off = (uint32_t)(kk * B_ROW_B + n4 * 2);
                *(uint2*)(sm + SM_BHI + off) = make_uint2(h0, h1);
                *(uint2*)(sm + SM_BLO + off) = make_uint2(l0, l1);
            }
        }
        __syncthreads();

#pragma unroll
        for (int ks = 0; ks < 2; ks++) {
            const uint32_t kb16 = (uint32_t)(ks * 16);
            uint32_t bhi[4][2], blo[4][2];
#pragma unroll
            for (int fn = 0; fn < 4; fn++) {
                uint32_t nb = (uint32_t)((wc * 32 + fn * 8) * 2);
                uint32_t ba = sbase + kb16 * B_ROW_B + b_lane_off + nb;
                ldsm_x2_t(bhi[fn], ba + SM_BHI);
                ldsm_x2_t(blo[fn], ba + SM_BLO);
            }
#pragma unroll
            for (int fm = 0; fm < 4; fm++) {
                uint32_t row0 = (uint32_t)(wr * 64 + fm * 16);
                uint32_t aa = sbase + row0 * A_ROW_B + kb16 * 2 + a_lane_off;
                uint32_t ahi[4], alo[4];
                ldsm_x4(ahi, aa + SM_AHI);
                ldsm_x4(alo, aa + SM_ALO);
#pragma unroll
                for (int fn = 0; fn < 4; fn++) {
                    mma_bf16(acc[fm][fn], ahi, bhi[fn]);
                    mma_bf16(acc[fm][fn], ahi, blo[fn]);
                    mma_bf16(acc[fm][fn], alo, bhi[fn]);
                }
            }
        }
        __syncthreads();
    }

#pragma unroll
    for (int fm = 0; fm < 4; fm++) {
#pragma unroll
        for (int fn = 0; fn < 4; fn++) {
            int r0 = brow + wr * 64 + fm * 16 + (lane >> 2);
            int c0 = bcol + wc * 32 + fn * 8 + (lane & 3) * 2;
            *(float2*)&C[(size_t)r0 * N + c0] =
                make_float2(acc[fm][fn][0], acc[fm][fn][1]);
            *(float2*)&C[(size_t)(r0 + 8) * N + c0] =
                make_float2(acc[fm][fn][2], acc[fm][fn][3]);
        }
    }
}

// ---------------------------------------------------------------------------
// Tensor-core causal flash attention.
// grid (16 qblocks, 32 qheads), 256 threads (8 warps).
// BQ=128 (warp = 16 rows), BK=64, DH=128.
// Q in register A-frags (hi/lo, pre-scaled). K transposed to smem [dh][key]
// (verified [k][n]+ldsm.trans path); V natural [key][dh]. 3-term bf16 splits.
// ---------------------------------------------------------------------------
#define KT_ROW   144
#define V_ROW    272
#define ASM_KTHI 0
#define ASM_KTLO (128 * KT_ROW)                 // 18432
#define ASM_VHI  (2 * 128 * KT_ROW)             // 36864
#define ASM_VLO  (ASM_VHI + 64 * V_ROW)         // 54272
#define ASM_STG  (ASM_VLO + 64 * V_ROW)         // 71680
#define STG_ROW  133
#define ATT_SMEM (ASM_STG + 64 * STG_ROW * 4)   // 105728

__global__ __launch_bounds__(256, 1) void attn_tc(
    const float* __restrict__ q,   // [L, 4096]
    const float* __restrict__ k,   // [L, 2048]
    const float* __restrict__ v,   // [L, 2048]
    float* __restrict__ o)         // [32][L][128]
{
    extern __shared__ char sm[];
    const int qb   = blockIdx.x;
    const int qh   = blockIdx.y;
    const int kvh  = qh >> 1;
    const int tid  = threadIdx.x;
    const int w    = tid >> 5;
    const int lane = tid & 31;
    const uint32_t sbase = smem_u32(sm);
    const float scale = 0.08838834764831843f;   // 1/sqrt(128)

    // ---- Q fragments in registers (hi/lo bf16, pre-scaled) ----
    uint32_t qhi[8][4], qlo[8][4];
    {
        const int r0 = qb * 128 + w * 16 + (lane >> 2);
        const float* q0 = q + (size_t)r0 * 4096 + qh * 128 + (lane & 3) * 2;
        const float* q1 = q0 + 8 * 4096;
#pragma unroll
        for (int kf = 0; kf < 8; kf++) {
            float2 x0 = *(const float2*)(q0 + kf * 16);
            float2 x1 = *(const float2*)(q1 + kf * 16);
            float2 x2 = *(const float2*)(q0 + kf * 16 + 8);
            float2 x3 = *(const float2*)(q1 + kf * 16 + 8);
            split2(x0.x * scale, x0.y * scale, qhi[kf][0], qlo[kf][0]);
            split2(x1.x * scale, x1.y * scale, qhi[kf][1], qlo[kf][1]);
            split2(x2.x * scale, x2.y * scale, qhi[kf][2], qlo[kf][2]);
            split2(x3.x * scale, x3.y * scale, qhi[kf][3], qlo[kf][3]);
        }
    }

    float m0 = -1e30f, m1 = -1e30f, l0 = 0.f, l1 = 0.f;
    float O[16][4];
#pragma unroll
    for (int d = 0; d < 16; d++)
#pragma unroll
        for (int t = 0; t < 4; t++) O[d][t] = 0.f;

    float* stg = (float*)(sm + ASM_STG);
    const int kb_max = 2 * qb + 1;

    for (int kb = 0; kb <= kb_max; kb++) {
        __syncthreads();   // previous iteration's smem readers done

        // ---- stage K tile fp32 [64][133] + V tile hi/lo directly ----
#pragma unroll
        for (int i = 0; i < 8; i++) {
            int pos = tid + i * 256;            // 2048 = 64 keys x 32 quads
            int key = pos >> 5, dq = pos & 31;
            const size_t gro = (size_t)(kb * 64 + key) * 2048 + kvh * 128 + dq * 4;
            float4 kv4 = *(const float4*)(k + gro);
            float* dst = stg + key * STG_ROW + dq * 4;
            dst[0] = kv4.x; dst[1] = kv4.y; dst[2] = kv4.z; dst[3] = kv4.w;
            float4 vv = *(const float4*)(v + gro);
            uint32_t h0, lw0, h1, lw1;
            split2(vv.x, vv.y, h0, lw0);
            split2(vv.z, vv.w, h1, lw1);
            char* vh = sm + ASM_VHI + key * V_ROW + dq * 8;
            char* vl = sm + ASM_VLO + key * V_ROW + dq * 8;
            *(uint32_t*)vh = h0; *(uint32_t*)(vh + 4) = h1;
            *(uint32_t*)vl = lw0; *(uint32_t*)(vl + 4) = lw1;
        }
        __syncthreads();   // stage visible

        // ---- build KT [dh][key] hi/lo from staged fp32 ----
#pragma unroll
        for (int i = 0; i < 16; i++) {
            int pos = tid + i * 256;            // 4096 = 128 dh x 32 key-pairs
            int dh = pos >> 5, kp = pos & 31;
            float f0 = stg[(2 * kp) * STG_ROW + dh];
            float f1 = stg[(2 * kp + 1) * STG_ROW + dh];
            uint32_t hp, lp;
            split2(f0, f1, hp, lp);
            *(uint32_t*)(sm + ASM_KTHI + dh * KT_ROW + kp * 4) = hp;
            *(uint32_t*)(sm + ASM_KTLO + dh * KT_ROW + kp * 4) = lp;
        }
        __syncthreads();   // KT visible

        // ---- S = Q K^T (16 x 64 per warp, 3-term) ----
        float s[8][4];
#pragma unroll
        for (int j = 0; j < 8; j++) {
            s[j][0] = s[j][1] = s[j][2] = s[j][3] = 0.f;
#pragma unroll
            for (int kf = 0; kf < 8; kf++) {
                uint32_t addr = sbase + (uint32_t)((kf * 16 + (lane & 15)) * KT_ROW + j * 16);
                uint32_t bh[2], bl[2];
                ldsm_x2_t(bh, addr + ASM_KTHI);
                ldsm_x2_t(bl, addr + ASM_KTLO);
                mma_bf16(s[j], qhi[kf], bh);
                mma_bf16(s[j], qhi[kf], bl);
                mma_bf16(s[j], qlo[kf], bh);
            }
        }

        // ---- causal mask (diag blocks only) ----
        if (kb >= 2 * qb) {
            int row0 = qb * 128 + w * 16 + (lane >> 2);
            int colb = kb * 64 + (lane & 3) * 2;
#pragma unroll
            for (int j = 0; j < 8; j++) {
                int c0 = colb + j * 8;
                if (c0     > row0)     s[j][0] = -1e30f;
                if (c0 + 1 > row0)     s[j][1] = -1e30f;
                if (c0     > row0 + 8) s[j][2] = -1e30f;
                if (c0 + 1 > row0 + 8) s[j][3] = -1e30f;
            }
        }

        // ---- online softmax (row = quad; shfl xor 1,2) ----
        float mx0 = -1e30f, mx1 = -1e30f;
#pragma unroll
        for (int j = 0; j < 8; j++) {
            mx0 = fmaxf(mx0, fmaxf(s[j][0], s[j][1]));
            mx1 = fmaxf(mx1, fmaxf(s[j][2], s[j][3]));
        }
        mx0 = fmaxf(mx0, __shfl_xor_sync(0xffffffffu, mx0, 1));
        mx0 = fmaxf(mx0, __shfl_xor_sync(0xffffffffu, mx0, 2));
        mx1 = fmaxf(mx1, __shfl_xor_sync(0xffffffffu, mx1, 1));
        mx1 = fmaxf(mx1, __shfl_xor_sync(0xffffffffu, mx1, 2));
        float mn0 = fmaxf(m0, mx0), mn1 = fmaxf(m1, mx1);
        float a0 = __expf(m0 - mn0), a1 = __expf(m1 - mn1);
        m0 = mn0; m1 = mn1;
        float rs0 = 0.f, rs1 = 0.f;
#pragma unroll
        for (int j = 0; j < 8; j++) {
            s[j][0] = __expf(s[j][0] - mn0);
            s[j][1] = __expf(s[j][1] - mn0);
            s[j][2] = __expf(s[j][2] - mn1);
            s[j][3] = __expf(s[j][3] - mn1);
            rs0 += s[j][0] + s[j][1];
            rs1 += s[j][2] + s[j][3];
        }
        rs0 += __shfl_xor_sync(0xffffffffu, rs0, 1);
        rs0 += __shfl_xor_sync(0xffffffffu, rs0, 2);
        rs1 += __shfl_xor_sync(0xffffffffu, rs1, 1);
        rs1 += __shfl_xor_sync(0xffffffffu, rs1, 2);
        l0 = l0 * a0 + rs0;
        l1 = l1 * a1 + rs1;
#pragma unroll
        for (int d = 0; d < 16; d++) {
            O[d][0] *= a0; O[d][1] *= a0;
            O[d][2] *= a1; O[d][3] *= a1;
        }

        // ---- P C-frags -> A-frags (pure register repack), hi/lo ----
        uint32_t phi[4][4], plo[4][4];
#pragma unroll
        for (int kf2 = 0; kf2 < 4; kf2++) {
            split2(s[2 * kf2][0],     s[2 * kf2][1],     phi[kf2][0], plo[kf2][0]);
            split2(s[2 * kf2][2],     s[2 * kf2][3],     phi[kf2][1], plo[kf2][1]);
            split2(s[2 * kf2 + 1][0], s[2 * kf2 + 1][1], phi[kf2][2], plo[kf2][2]);
            split2(s[2 * kf2 + 1][2], s[2 * kf2 + 1][3], phi[kf2][3], plo[kf2][3]);
        }

        // ---- O += P @ V (3-term) ----
#pragma unroll
        for (int d = 0; d < 16; d++) {
#pragma unroll
            for (int kf2 = 0; kf2 < 4; kf2++) {
                uint32_t addr = sbase + (uint32_t)((kf2 * 16 + (lane & 15)) * V_ROW + d * 16);
                uint32_t bh[2], bl[2];
                ldsm_x2_t(bh, addr + ASM_VHI);
                ldsm_x2_t(bl, addr + ASM_VLO);
                mma_bf16(O[d], phi[kf2], bh);
                mma_bf16(O[d], phi[kf2], bl);
                mma_bf16(O[d], plo[kf2], bh);
            }
        }
    }

    // ---- normalize + write ----
    float i0 = 1.f / l0, i1 = 1.f / l1;
    int r0 = qb * 128 + w * 16 + (lane >> 2);
#pragma unroll
    for (int d = 0; d < 16; d++) {
        int col = d * 8 + (lane & 3) * 2;
        *(float2*)&o[((size_t)qh * L_SEQ + r0) * 128 + col] =
            make_float2(O[d][0] * i0, O[d][1] * i0);
        *(float2*)&o[((size_t)qh * L_SEQ + r0 + 8) * 128 + col] =
            make_float2(O[d][2] * i1, O[d][3] * i1);
    }
}

// ---------------------------------------------------------------------------
// RoPE in-place (fp32)
// ---------------------------------------------------------------------------
__global__ void rope_kernel(float* __restrict__ buf, int stride)
{
    const int l = blockIdx.x;
    const int h = blockIdx.y;
    const int d = threadIdx.x;

    float inv_freq = exp2f(-(float)d * (13.287712379549449f / 64.f));
    float ang = (float)l * inv_freq;
    float s, c;
    sincosf(ang, &s, &c);

    float* p = buf + (size_t)l * stride + h * DHEAD;
    float x1 = p[d];
    float x2 = p[d + 64];
    p[d]      = x1 * c - x2 * s;
    p[d + 64] = x2 * c + x1 * s;
}

// ---------------------------------------------------------------------------
// lam = sigmoid(x @ W_lam + b_lam)
// ---------------------------------------------------------------------------
__global__ void lam_kernel(const float* __restrict__ x,
                           const float* __restrict__ Wl,
                           const float* __restrict__ bl,
                           float* __restrict__ lam)
{
    __shared__ float part[256];
    const int l = blockIdx.x;
    const int t = threadIdx.x;
    const int h = t & 15;
    const int p = t >> 4;

    float s = 0.f;
#pragma unroll 4
    for (int j = 0; j < 128; j++) {
        int kk = p * 128 + j;
        s += x[(size_t)l * D_MODEL + kk] * Wl[(size_t)kk * NHEADS + h];
    }
    part[t] = s;
    __syncthreads();
    if (t < NHEADS) {
        float tot = bl[t];
#pragma unroll
        for (int p2 = 0; p2 < 16; p2++) tot += part[p2 * 16 + t];
        lam[(size_t)l * NHEADS + t] = 1.f / (1.f + __expf(-tot));
    }
}

// ---------------------------------------------------------------------------
// combine: out[l, h*128+d] = attn1 - lam[l,h] * attn2
// ---------------------------------------------------------------------------
__global__ void combine_kernel(const float* __restrict__ attn,
                               const float* __restrict__ lam,
                               float* __restrict__ out)
{
    int idx = blockIdx.x * 256 + threadIdx.x;
    int l = idx >> 11;
    int c = idx & 2047;
    int h = c >> 7;
    int d = c & 127;
    float a1 = attn[((size_t)(2 * h)     * L_SEQ + l) * DHEAD + d];
    float a2 = attn[((size_t)(2 * h + 1) * L_SEQ + l) * DHEAD + d];
    out[idx] = a1 - lam[(size_t)l * NHEADS + h] * a2;
}

// ---------------------------------------------------------------------------
// kernel_launch
// inputs: 0=x 1=W_DKV 2=W_UK 3=W_UV 4=W_DQ 5=W_UQ 6=W_lam 7=b_lam 8=W_out
// ---------------------------------------------------------------------------
extern "C" void kernel_launch(void* const* d_in, const int* in_sizes, int n_in,
                              void* d_out, int out_size)
{
    const float* x     = (const float*)d_in[0];
    const float* W_DKV = (const float*)d_in[1];
    const float* W_UK  = (const float*)d_in[2];
    const float* W_UV  = (const float*)d_in[3];
    const float* W_DQ  = (const float*)d_in[4];
    const float* W_UQ  = (const float*)d_in[5];
    const float* W_lam = (const float*)d_in[6];
    const float* b_lam = (const float*)d_in[7];
    const float* W_out = (const float*)d_in[8];
    float* out = (float*)d_out;

    float *ckv, *kbuf, *vbuf, *cq, *qbuf, *attn, *lam, *comb;
    cudaGetSymbolAddress((void**)&ckv,  g_ckv);
    cudaGetSymbolAddress((void**)&kbuf, g_k);
    cudaGetSymbolAddress((void**)&vbuf, g_v);
    cudaGetSymbolAddress((void**)&cq,   g_cq);
    cudaGetSymbolAddress((void**)&qbuf, g_q);
    cudaGetSymbolAddress((void**)&attn, g_attn);
    cudaGetSymbolAddress((void**)&lam,  g_lam);
    cudaGetSymbolAddress((void**)&comb, g_comb);

    // projections (warp-level bf16 3-term tensor-core GEMM)
    tc_gemm<<<dim3(DC / 128,      L_SEQ / 128), 256>>>(x,   W_DKV, ckv,  L_SEQ, DC,      D_MODEL);
    tc_gemm<<<dim3(D_MODEL / 128, L_SEQ / 128), 256>>>(ckv, W_UK,  kbuf, L_SEQ, D_MODEL, DC);
    tc_gemm<<<dim3(D_MODEL / 128, L_SEQ / 128), 256>>>(ckv, W_UV,  vbuf, L_SEQ, D_MODEL, DC);
    tc_gemm<<<dim3(DCQ / 128,     L_SEQ / 128), 256>>>(x,   W_DQ,  cq,   L_SEQ, DCQ,     D_MODEL);
    tc_gemm<<<dim3(4096 / 128,    L_SEQ / 128), 256>>>(cq,  W_UQ,  qbuf, L_SEQ, 4096,    DCQ);

    // RoPE
    rope_kernel<<<dim3(L_SEQ, QHEADS), 64>>>(qbuf, 2 * D_MODEL);
    rope_kernel<<<dim3(L_SEQ, NHEADS), 64>>>(kbuf, D_MODEL);

    // gate
    lam_kernel<<<L_SEQ, 256>>>(x, W_lam, b_lam, lam);

    // attention (tensor-core flash)
    cudaFuncSetAttribute(attn_tc, cudaFuncAttributeMaxDynamicSharedMemorySize, ATT_SMEM);
    attn_tc<<<dim3(L_SEQ / 128, QHEADS), 256, ATT_SMEM>>>(qbuf, kbuf, vbuf, attn);

    // differential combine
    combine_kernel<<<(L_SEQ * D_MODEL) / 256, 256>>>(attn, lam, comb);

    // output projection
    tc_gemm<<<dim3(D_MODEL / 128, L_SEQ / 128), 256>>>(comb, W_out, out, L_SEQ, D_MODEL, D_MODEL);
}

// round 10
// speedup vs baseline: 3.5922x; 1.1201x over previous
#include <cuda_runtime.h>
#include <cuda_bf16.h>
#include <math.h>
#include <stdint.h>

#define L_SEQ   2048
#define D_MODEL 2048
#define NHEADS  16
#define DHEAD   128
#define DC      512
#define DCQ     1024
#define QHEADS  32

// ---------------------------------------------------------------------------
// Scratch (static device globals -- no runtime allocation allowed).
// All bf16 data stored as POD unsigned short (raw bit patterns) so no
// __device__ global has a class type (avoids dynamic-init compile failure).
// ---------------------------------------------------------------------------
__device__ float g_k   [L_SEQ * D_MODEL];
__device__ float g_q   [L_SEQ * 2 * D_MODEL];
__device__ float g_attn[QHEADS * L_SEQ * DHEAD];
__device__ float g_lam [L_SEQ * NHEADS];

__device__ unsigned short g_xhi [L_SEQ * D_MODEL],    g_xlo [L_SEQ * D_MODEL];
__device__ unsigned short g_wdkvh[D_MODEL * DC],      g_wdkvl[D_MODEL * DC];
__device__ unsigned short g_wukh [DC * D_MODEL],      g_wukl [DC * D_MODEL];
__device__ unsigned short g_wuvh [DC * D_MODEL],      g_wuvl [DC * D_MODEL];
__device__ unsigned short g_wdqh [D_MODEL * DCQ],     g_wdql [D_MODEL * DCQ];
__device__ unsigned short g_wuqh [DCQ * 2 * D_MODEL], g_wuql [DCQ * 2 * D_MODEL];
__device__ unsigned short g_wouth[D_MODEL * D_MODEL], g_woutl[D_MODEL * D_MODEL];
__device__ unsigned short g_ckvh [L_SEQ * DC],        g_ckvl [L_SEQ * DC];
__device__ unsigned short g_cqh  [L_SEQ * DCQ],       g_cql  [L_SEQ * DCQ];
__device__ unsigned short g_vh   [L_SEQ * D_MODEL],   g_vl   [L_SEQ * D_MODEL];
__device__ unsigned short g_kth  [D_MODEL * L_SEQ],   g_ktl  [D_MODEL * L_SEQ];
__device__ unsigned short g_cmbh [L_SEQ * D_MODEL],   g_cmbl [L_SEQ * D_MODEL];

// ---------------------------------------------------------------------------
// Helpers (sm_80-baseline features only)
// ---------------------------------------------------------------------------
__device__ __forceinline__ uint32_t smem_u32(const void* p) {
    uint32_t r;
    asm("{ .reg .u64 t; cvta.to.shared.u64 t, %1; cvt.u32.u64 %0, t; }"
        : "=r"(r) : "l"(p));
    return r;
}
__device__ __forceinline__ void split_bf(float v, uint16_t& h, uint16_t& l) {
    __nv_bfloat16 hb = __float2bfloat16_rn(v);
    float hf = __bfloat162float(hb);
    __nv_bfloat16 lb = __float2bfloat16_rn(v - hf);
    h = *(uint16_t*)&hb;
    l = *(uint16_t*)&lb;
}
__device__ __forceinline__ void split2(float a, float b, uint32_t& hp, uint32_t& lp) {
    uint16_t ha, la, hb, lb;
    split_bf(a, ha, la);
    split_bf(b, hb, lb);
    hp = (uint32_t)ha | ((uint32_t)hb << 16);
    lp = (uint32_t)la | ((uint32_t)lb << 16);
}
__device__ __forceinline__ void ldsm_x4(uint32_t* r, uint32_t addr) {
    asm volatile("ldmatrix.sync.aligned.m8n8.x4.shared.b16 {%0,%1,%2,%3}, [%4];"
                 : "=r"(r[0]), "=r"(r[1]), "=r"(r[2]), "=r"(r[3]) : "r"(addr));
}
__device__ __forceinline__ void ldsm_x2_t(uint32_t* r, uint32_t addr) {
    asm volatile("ldmatrix.sync.aligned.m8n8.x2.trans.shared.b16 {%0,%1}, [%2];"
                 : "=r"(r[0]), "=r"(r[1]) : "r"(addr));
}
__device__ __forceinline__ void mma_bf16(float* d, const uint32_t* a, const uint32_t* b) {
    asm volatile(
        "mma.sync.aligned.m16n8k16.row.col.f32.bf16.bf16.f32 "
        "{%0,%1,%2,%3}, {%4,%5,%6,%7}, {%8,%9}, {%0,%1,%2,%3};"
        : "+f"(d[0]), "+f"(d[1]), "+f"(d[2]), "+f"(d[3])
        : "r"(a[0]), "r"(a[1]), "r"(a[2]), "r"(a[3]), "r"(b[0]), "r"(b[1]));
}

// ---------------------------------------------------------------------------
// split_kernel: fp32 -> bf16 hi/lo bit-patterns (elementwise)
// ---------------------------------------------------------------------------
__global__ void split_kernel(const float* __restrict__ src,
                             uint16_t* __restrict__ hi, uint16_t* __restrict__ lo)
{
    int i = blockIdx.x * 256 + threadIdx.x;       // float4 index
    float4 v = ((const float4*)src)[i];
    uint32_t h0, l0, h1, l1;
    split2(v.x, v.y, h0, l0);
    split2(v.z, v.w, h1, l1);
    ((uint2*)hi)[i] = make_uint2(h0, h1);
    ((uint2*)lo)[i] = make_uint2(l0, l1);
}

// ---------------------------------------------------------------------------
// ktrans_split: k fp32 [L][2048] -> kT hi/lo [16][128][L]
// block (32,8), grid (L/32, 4, 16)
// ---------------------------------------------------------------------------
__global__ void ktrans_split(const float* __restrict__ k,
                             uint16_t* __restrict__ kth, uint16_t* __restrict__ ktl)
{
    __shared__ float tile[32][33];
    const int l0  = blockIdx.x * 32;
    const int d0  = blockIdx.y * 32;
    const int h   = blockIdx.z;
    const int tx  = threadIdx.x;
    const int ty  = threadIdx.y;

#pragma unroll
    for (int i = 0; i < 4; i++) {
        int lr = ty + i * 8;
        tile[lr][tx] = k[(size_t)(l0 + lr) * D_MODEL + h * DHEAD + d0 + tx];
    }
    __syncthreads();
#pragma unroll
    for (int i = 0; i < 4; i++) {
        int dr = ty + i * 8;
        float v = tile[tx][dr];
        uint16_t hh, ll;
        split_bf(v, hh, ll);
        size_t off = (size_t)(h * DHEAD + d0 + dr) * L_SEQ + l0 + tx;
        kth[off] = hh;
        ktl[off] = ll;
    }
}

// ---------------------------------------------------------------------------
// TC GEMM v3: pre-split bf16 operands, synchronous single-stage smem
// (proven R5 skeleton). C[M,N] = A[M,K] @ B[K,N]; 128x128 tile, BK=32.
// mode 0: fp32 C.  mode 1: bf16 hi/lo bit-pattern C.
// ---------------------------------------------------------------------------
#define GA_ROW 80
#define GB_ROW 272
#define G_AHI  0
#define G_ALO  (128 * GA_ROW)
#define G_BHI  (2 * 128 * GA_ROW)
#define G_BLO  (G_BHI + 32 * GB_ROW)
#define G_TOT  (G_BLO + 32 * GB_ROW)     // 37888

__global__ __launch_bounds__(256, 2)
void tc_gemm3(const uint16_t* __restrict__ Ahi, const uint16_t* __restrict__ Alo,
              const uint16_t* __restrict__ Bhi, const uint16_t* __restrict__ Blo,
              float* __restrict__ C, uint16_t* __restrict__ Chi, uint16_t* __restrict__ Clo,
              int M, int N, int K, int mode)
{
    __shared__ __align__(16) char sm[G_TOT];
    const int tid  = threadIdx.x;
    const int wid  = tid >> 5;
    const int lane = tid & 31;
    const int wr   = wid >> 2;
    const int wc   = wid & 3;
    const int brow = blockIdx.y * 128;
    const int bcol = blockIdx.x * 128;

    const uint32_t sbase = smem_u32(sm);

    float acc[4][4][4];
#pragma unroll
    for (int i = 0; i < 4; i++)
#pragma unroll
        for (int j = 0; j < 4; j++)
#pragma unroll
            for (int t = 0; t < 4; t++) acc[i][j][t] = 0.f;

    const uint32_t a_lane_off = (uint32_t)((lane & 15) * GA_ROW + ((lane >> 4) << 3) * 2);
    const uint32_t b_lane_off = (uint32_t)((lane & 15) * GB_ROW);

    const int nIter = K >> 5;
    for (int it = 0; it < nIter; it++) {
        const int k0 = it << 5;
#pragma unroll
        for (int c = 0; c < 8; c++) {
            int id = c * 256 + tid;
            if (c < 2) {
                int row = id >> 2, c16 = id & 3;
                uint4 v = *(const uint4*)(Ahi + (size_t)(brow + row) * K + k0 + c16 * 8);
                *(uint4*)(sm + G_AHI + row * GA_ROW + c16 * 16) = v;
            } else if (c < 4) {
                int j = id - 512;
                int row = j >> 2, c16 = j & 3;
                uint4 v = *(const uint4*)(Alo + (size_t)(brow + row) * K + k0 + c16 * 8);
                *(uint4*)(sm + G_ALO + row * GA_ROW + c16 * 16) = v;
            } else if (c < 6) {
                int j = id - 1024;
                int kk = j >> 4, c16 = j & 15;
                uint4 v = *(const uint4*)(Bhi + (size_t)(k0 + kk) * N + bcol + c16 * 8);
                *(uint4*)(sm + G_BHI + kk * GB_ROW + c16 * 16) = v;
            } else {
                int j = id - 1536;
                int kk = j >> 4, c16 = j & 15;
                uint4 v = *(const uint4*)(Blo + (size_t)(k0 + kk) * N + bcol + c16 * 8);
                *(uint4*)(sm + G_BLO + kk * GB_ROW + c16 * 16) = v;
            }
        }
        __syncthreads();

#pragma unroll
        for (int ks = 0; ks < 2; ks++) {
            const uint32_t kb16 = (uint32_t)(ks * 16);
            uint32_t bhiF[4][2], bloF[4][2];
#pragma unroll
            for (int fn = 0; fn < 4; fn++) {
                uint32_t nb = (uint32_t)((wc * 32 + fn * 8) * 2);
                uint32_t ba = sbase + kb16 * GB_ROW + b_lane_off + nb;
                ldsm_x2_t(bhiF[fn], ba + G_BHI);
                ldsm_x2_t(bloF[fn], ba + G_BLO);
            }
#pragma unroll
            for (int fm = 0; fm < 4; fm++) {
                uint32_t row0 = (uint32_t)(wr * 64 + fm * 16);
                uint32_t aa = sbase + row0 * GA_ROW + kb16 * 2 + a_lane_off;
                uint32_t ahiF[4], aloF[4];
                ldsm_x4(ahiF, aa + G_AHI);
                ldsm_x4(aloF, aa + G_ALO);
#pragma unroll
                for (int fn = 0; fn < 4; fn++) {
                    mma_bf16(acc[fm][fn], ahiF, bhiF[fn]);
                    mma_bf16(acc[fm][fn], ahiF, bloF[fn]);
                    mma_bf16(acc[fm][fn], aloF, bhiF[fn]);
                }
            }
        }
        __syncthreads();
    }

    if (mode == 0) {
#pragma unroll
        for (int fm = 0; fm < 4; fm++)
#pragma unroll
            for (int fn = 0; fn < 4; fn++) {
                int r0 = brow + wr * 64 + fm * 16 + (lane >> 2);
                int c0 = bcol + wc * 32 + fn * 8 + (lane & 3) * 2;
                *(float2*)&C[(size_t)r0 * N + c0] =
                    make_float2(acc[fm][fn][0], acc[fm][fn][1]);
                *(float2*)&C[(size_t)(r0 + 8) * N + c0] =
                    make_float2(acc[fm][fn][2], acc[fm][fn][3]);
            }
    } else {
#pragma unroll
        for (int fm = 0; fm < 4; fm++)
#pragma unroll
            for (int fn = 0; fn < 4; fn++) {
                int r0 = brow + wr * 64 + fm * 16 + (lane >> 2);
                int c0 = bcol + wc * 32 + fn * 8 + (lane & 3) * 2;
                uint32_t h0, l0, h1, l1;
                split2(acc[fm][fn][0], acc[fm][fn][1], h0, l0);
                split2(acc[fm][fn][2], acc[fm][fn][3], h1, l1);
                *(uint32_t*)&Chi[(size_t)r0 * N + c0]       = h0;
                *(uint32_t*)&Clo[(size_t)r0 * N + c0]       = l0;
                *(uint32_t*)&Chi[(size_t)(r0 + 8) * N + c0] = h1;
                *(uint32_t*)&Clo[(size_t)(r0 + 8) * N + c0] = l1;
            }
    }
}

// ---------------------------------------------------------------------------
// Tensor-core causal flash attention v3: pre-split KT/V, synchronous loads
// (proven R6 skeleton; staging/transpose/split deleted).
// grid (16 qblocks, 32 qheads), 256 threads. BQ=128, BK=64.
// ---------------------------------------------------------------------------
#define KT_ROW   144
#define V_ROW    272
#define A_KTHI   0
#define A_KTLO   (128 * KT_ROW)                 // 18432
#define A_VHI    (2 * 128 * KT_ROW)             // 36864
#define A_VLO    (A_VHI + 64 * V_ROW)           // 54272
#define ATT_SMEM (A_VLO + 64 * V_ROW)           // 71680

__global__ __launch_bounds__(256, 1) void attn_tc3(
    const float* __restrict__ q,
    const uint16_t* __restrict__ kth, const uint16_t* __restrict__ ktl,
    const uint16_t* __restrict__ vh,  const uint16_t* __restrict__ vl,
    float* __restrict__ o)
{
    extern __shared__ char sm[];
    const int qb   = blockIdx.x;
    const int qh   = blockIdx.y;
    const int kvh  = qh >> 1;
    const int tid  = threadIdx.x;
    const int w    = tid >> 5;
    const int lane = tid & 31;
    const uint32_t sbase = smem_u32(sm);
    const float scale = 0.08838834764831843f;

    // Q fragments in registers (hi/lo, pre-scaled) -- once per CTA
    uint32_t qhi[8][4], qlo[8][4];
    {
        const int r0 = qb * 128 + w * 16 + (lane >> 2);
        const float* q0 = q + (size_t)r0 * 4096 + qh * 128 + (lane & 3) * 2;
        const float* q1 = q0 + 8 * 4096;
#pragma unroll
        for (int kf = 0; kf < 8; kf++) {
            float2 x0 = *(const float2*)(q0 + kf * 16);
            float2 x1 = *(const float2*)(q1 + kf * 16);
            float2 x2 = *(const float2*)(q0 + kf * 16 + 8);
            float2 x3 = *(const float2*)(q1 + kf * 16 + 8);
            split2(x0.x * scale, x0.y * scale, qhi[kf][0], qlo[kf][0]);
            split2(x1.x * scale, x1.y * scale, qhi[kf][1], qlo[kf][1]);
            split2(x2.x * scale, x2.y * scale, qhi[kf][2], qlo[kf][2]);
            split2(x3.x * scale, x3.y * scale, qhi[kf][3], qlo[kf][3]);
        }
    }

    float m0 = -1e30f, m1 = -1e30f, l0 = 0.f, l1 = 0.f;
    float O[16][4];
#pragma unroll
    for (int d = 0; d < 16; d++)
#pragma unroll
        for (int t = 0; t < 4; t++) O[d][t] = 0.f;

    const int kb_max = 2 * qb + 1;
    for (int kb = 0; kb <= kb_max; kb++) {
        __syncthreads();   // previous iteration's readers done

        // ---- load KT hi/lo [128][64] + V hi/lo [64][128]: 16 x 16B each ----
#pragma unroll
        for (int c = 0; c < 16; c++) {
            int id = c * 256 + tid;
            if (c < 4) {
                int dh = id >> 3, kc = id & 7;
                uint4 v = *(const uint4*)(kth + (size_t)(kvh * DHEAD + dh) * L_SEQ + kb * 64 + kc * 8);
                *(uint4*)(sm + A_KTHI + dh * KT_ROW + kc * 16) = v;
            } else if (c < 8) {
                int j = id - 1024;
                int dh = j >> 3, kc = j & 7;
                uint4 v = *(const uint4*)(ktl + (size_t)(kvh * DHEAD + dh) * L_SEQ + kb * 64 + kc * 8);
                *(uint4*)(sm + A_KTLO + dh * KT_ROW + kc * 16) = v;
            } else if (c < 12) {
                int j = id - 2048;
                int key = j >> 4, c16 = j & 15;
                uint4 v = *(const uint4*)(vh + (size_t)(kb * 64 + key) * D_MODEL + kvh * DHEAD + c16 * 8);
                *(uint4*)(sm + A_VHI + key * V_ROW + c16 * 16) = v;
            } else {
                int j = id - 3072;
                int key = j >> 4, c16 = j & 15;
                uint4 v = *(const uint4*)(vl + (size_t)(kb * 64 + key) * D_MODEL + kvh * DHEAD + c16 * 8);
                *(uint4*)(sm + A_VLO + key * V_ROW + c16 * 16) = v;
            }
        }
        __syncthreads();

        // ---- S = Q K^T (3-term) ----
        float s[8][4];
#pragma unroll
        for (int j = 0; j < 8; j++) {
            s[j][0] = s[j][1] = s[j][2] = s[j][3] = 0.f;
#pragma unroll
            for (int kf = 0; kf < 8; kf++) {
                uint32_t addr = sbase + (uint32_t)((kf * 16 + (lane & 15)) * KT_ROW + j * 16);
                uint32_t bh[2], bl[2];
                ldsm_x2_t(bh, addr + A_KTHI);
                ldsm_x2_t(bl, addr + A_KTLO);
                mma_bf16(s[j], qhi[kf], bh);
                mma_bf16(s[j], qhi[kf], bl);
                mma_bf16(s[j], qlo[kf], bh);
            }
        }

        // ---- causal mask (diag tiles only) ----
        if (kb >= 2 * qb) {
            int row0 = qb * 128 + w * 16 + (lane >> 2);
            int colb = kb * 64 + (lane & 3) * 2;
#pragma unroll
            for (int j = 0; j < 8; j++) {
                int c0 = colb + j * 8;
                if (c0     > row0)     s[j][0] = -1e30f;
                if (c0 + 1 > row0)     s[j][1] = -1e30f;
                if (c0     > row0 + 8) s[j][2] = -1e30f;
                if (c0 + 1 > row0 + 8) s[j][3] = -1e30f;
            }
        }

        // ---- online softmax (row = quad; shfl xor 1,2) ----
        float mx0 = -1e30f, mx1 = -1e30f;
#pragma unroll
        for (int j = 0; j < 8; j++) {
            mx0 = fmaxf(mx0, fmaxf(s[j][0], s[j][1]));
            mx1 = fmaxf(mx1, fmaxf(s[j][2], s[j][3]));
        }
        mx0 = fmaxf(mx0, __shfl_xor_sync(0xffffffffu, mx0, 1));
        mx0 = fmaxf(mx0, __shfl_xor_sync(0xffffffffu, mx0, 2));
        mx1 = fmaxf(mx1, __shfl_xor_sync(0xffffffffu, mx1, 1));
        mx1 = fmaxf(mx1, __shfl_xor_sync(0xffffffffu, mx1, 2));
        float mn0 = fmaxf(m0, mx0), mn1 = fmaxf(m1, mx1);
        float a0 = __expf(m0 - mn0), a1 = __expf(m1 - mn1);
        m0 = mn0; m1 = mn1;
        float rs0 = 0.f, rs1 = 0.f;
#pragma unroll
        for (int j = 0; j < 8; j++) {
            s[j][0] = __expf(s[j][0] - mn0);
            s[j][1] = __expf(s[j][1] - mn0);
            s[j][2] = __expf(s[j][2] - mn1);
            s[j][3] = __expf(s[j][3] - mn1);
            rs0 += s[j][0] + s[j][1];
            rs1 += s[j][2] + s[j][3];
        }
        rs0 += __shfl_xor_sync(0xffffffffu, rs0, 1);
        rs0 += __shfl_xor_sync(0xffffffffu, rs0, 2);
        rs1 += __shfl_xor_sync(0xffffffffu, rs1, 1);
        rs1 += __shfl_xor_sync(0xffffffffu, rs1, 2);
        l0 = l0 * a0 + rs0;
        l1 = l1 * a1 + rs1;
#pragma unroll
        for (int d = 0; d < 16; d++) {
            O[d][0] *= a0; O[d][1] *= a0;
            O[d][2] *= a1; O[d][3] *= a1;
        }

        // ---- P C-frags -> A-frags (register repack), hi/lo ----
        uint32_t phi[4][4], plo[4][4];
#pragma unroll
        for (int kf2 = 0; kf2 < 4; kf2++) {
            split2(s[2 * kf2][0],     s[2 * kf2][1],     phi[kf2][0], plo[kf2][0]);
            split2(s[2 * kf2][2],     s[2 * kf2][3],     phi[kf2][1], plo[kf2][1]);
            split2(s[2 * kf2 + 1][0], s[2 * kf2 + 1][1], phi[kf2][2], plo[kf2][2]);
            split2(s[2 * kf2 + 1][2], s[2 * kf2 + 1][3], phi[kf2][3], plo[kf2][3]);
        }

        // ---- O += P @ V (3-term) ----
#pragma unroll
        for (int d = 0; d < 16; d++) {
#pragma unroll
            for (int kf2 = 0; kf2 < 4; kf2++) {
                uint32_t addr = sbase + (uint32_t)((kf2 * 16 + (lane & 15)) * V_ROW + d * 16);
                uint32_t bh[2], bl[2];
                ldsm_x2_t(bh, addr + A_VHI);
                ldsm_x2_t(bl, addr + A_VLO);
                mma_bf16(O[d], phi[kf2], bh);
                mma_bf16(O[d], phi[kf2], bl);
                mma_bf16(O[d], plo[kf2], bh);
            }
        }
    }

    float i0 = 1.f / l0, i1 = 1.f / l1;
    int r0 = qb * 128 + w * 16 + (lane >> 2);
#pragma unroll
    for (int d = 0; d < 16; d++) {
        int col = d * 8 + (lane & 3) * 2;
        *(float2*)&o[((size_t)qh * L_SEQ + r0) * 128 + col] =
            make_float2(O[d][0] * i0, O[d][1] * i0);
        *(float2*)&o[((size_t)qh * L_SEQ + r0 + 8) * 128 + col] =
            make_float2(O[d][2] * i1, O[d][3] * i1);
    }
}

// ---------------------------------------------------------------------------
// RoPE in-place (fp32)
// ---------------------------------------------------------------------------
__global__ void rope_kernel(float* __restrict__ buf, int stride)
{
    const int l = blockIdx.x;
    const int h = blockIdx.y;
    const int d = threadIdx.x;

    float inv_freq = exp2f(-(float)d * (13.287712379549449f / 64.f));
    float ang = (float)l * inv_freq;
    float s, c;
    sincosf(ang, &s, &c);

    float* p = buf + (size_t)l * stride + h * DHEAD;
    float x1 = p[d];
    float x2 = p[d + 64];
    p[d]      = x1 * c - x2 * s;
    p[d + 64] = x2 * c + x1 * s;
}

// ---------------------------------------------------------------------------
// lam = sigmoid(x @ W_lam + b_lam)
// ---------------------------------------------------------------------------
__global__ void lam_kernel(const float* __restrict__ x,
                           const float* __restrict__ Wl,
                           const float* __restrict__ bl,
                           float* __restrict__ lam)
{
    __shared__ float part[256];
    const int l = blockIdx.x;
    const int t = threadIdx.x;
    const int h = t & 15;
    const int p = t >> 4;

    float s = 0.f;
#pragma unroll 4
    for (int j = 0; j < 128; j++) {
        int kk = p * 128 + j;
        s += x[(size_t)l * D_MODEL + kk] * Wl[(size_t)kk * NHEADS + h];
    }
    part[t] = s;
    __syncthreads();
    if (t < NHEADS) {
        float tot = bl[t];
#pragma unroll
        for (int p2 = 0; p2 < 16; p2++) tot += part[p2 * 16 + t];
        lam[(size_t)l * NHEADS + t] = 1.f / (1.f + __expf(-tot));
    }
}

// ---------------------------------------------------------------------------
// combine: emits bf16 hi/lo bit patterns directly for the Wout GEMM
// ---------------------------------------------------------------------------
__global__ void combine_kernel2(const float* __restrict__ attn,
                                const float* __restrict__ lam,
                                uint16_t* __restrict__ hi, uint16_t* __restrict__ lo)
{
    int idx = blockIdx.x * 256 + threadIdx.x;     // over L*1024 pairs
    int l  = idx >> 10;
    int cp = idx & 1023;
    int h  = cp >> 6;
    int dp = (cp & 63) * 2;
    float a1a = attn[((size_t)(2 * h)     * L_SEQ + l) * DHEAD + dp];
    float a1b = attn[((size_t)(2 * h)     * L_SEQ + l) * DHEAD + dp + 1];
    float a2a = attn[((size_t)(2 * h + 1) * L_SEQ + l) * DHEAD + dp];
    float a2b = attn[((size_t)(2 * h + 1) * L_SEQ + l) * DHEAD + dp + 1];
    float lm  = lam[(size_t)l * NHEADS + h];
    uint32_t hw, lw;
    split2(a1a - lm * a2a, a1b - lm * a2b, hw, lw);
    ((uint32_t*)hi)[idx] = hw;
    ((uint32_t*)lo)[idx] = lw;
}

// ---------------------------------------------------------------------------
// kernel_launch
// inputs: 0=x 1=W_DKV 2=W_UK 3=W_UV 4=W_DQ 5=W_UQ 6=W_lam 7=b_lam 8=W_out
// ---------------------------------------------------------------------------
extern "C" void kernel_launch(void* const* d_in, const int* in_sizes, int n_in,
                              void* d_out, int out_size)
{
    const float* x     = (const float*)d_in[0];
    const float* W_DKV = (const float*)d_in[1];
    const float* W_UK  = (const float*)d_in[2];
    const float* W_UV  = (const float*)d_in[3];
    const float* W_DQ  = (const float*)d_in[4];
    const float* W_UQ  = (const float*)d_in[5];
    const float* W_lam = (const float*)d_in[6];
    const float* b_lam = (const float*)d_in[7];
    const float* W_out = (const float*)d_in[8];
    float* out = (float*)d_out;

    float *kbuf, *qbuf, *attn, *lam;
    cudaGetSymbolAddress((void**)&kbuf, g_k);
    cudaGetSymbolAddress((void**)&qbuf, g_q);
    cudaGetSymbolAddress((void**)&attn, g_attn);
    cudaGetSymbolAddress((void**)&lam,  g_lam);

    uint16_t *xh,*xl,*wdkvh,*wdkvl,*wukh,*wukl,*wuvh,*wuvl,*wdqh,*wdql,
             *wuqh,*wuql,*wouth,*woutl,*ckvh,*ckvl,*cqh,*cql,*vh,*vl,
             *kth,*ktl,*cmbh,*cmbl;
    cudaGetSymbolAddress((void**)&xh,    g_xhi);   cudaGetSymbolAddress((void**)&xl,    g_xlo);
    cudaGetSymbolAddress((void**)&wdkvh, g_wdkvh); cudaGetSymbolAddress((void**)&wdkvl, g_wdkvl);
    cudaGetSymbolAddress((void**)&wukh,  g_wukh);  cudaGetSymbolAddress((void**)&wukl,  g_wukl);
    cudaGetSymbolAddress((void**)&wuvh,  g_wuvh);  cudaGetSymbolAddress((void**)&wuvl,  g_wuvl);
    cudaGetSymbolAddress((void**)&wdqh,  g_wdqh);  cudaGetSymbolAddress((void**)&wdql,  g_wdql);
    cudaGetSymbolAddress((void**)&wuqh,  g_wuqh);  cudaGetSymbolAddress((void**)&wuql,  g_wuql);
    cudaGetSymbolAddress((void**)&wouth, g_wouth); cudaGetSymbolAddress((void**)&woutl, g_woutl);
    cudaGetSymbolAddress((void**)&ckvh,  g_ckvh);  cudaGetSymbolAddress((void**)&ckvl,  g_ckvl);
    cudaGetSymbolAddress((void**)&cqh,   g_cqh);   cudaGetSymbolAddress((void**)&cql,   g_cql);
    cudaGetSymbolAddress((void**)&vh,    g_vh);    cudaGetSymbolAddress((void**)&vl,    g_vl);
    cudaGetSymbolAddress((void**)&kth,   g_kth);   cudaGetSymbolAddress((void**)&ktl,   g_ktl);
    cudaGetSymbolAddress((void**)&cmbh,  g_cmbh);  cudaGetSymbolAddress((void**)&cmbl,  g_cmbl);

    cudaFuncSetAttribute(attn_tc3, cudaFuncAttributeMaxDynamicSharedMemorySize, ATT_SMEM);

    // pre-split inputs (elementwise)
    split_kernel<<<(L_SEQ * D_MODEL) / 1024, 256>>>(x,     xh,    xl);
    split_kernel<<<(D_MODEL * DC) / 1024,    256>>>(W_DKV, wdkvh, wdkvl);
    split_kernel<<<(DC * D_MODEL) / 1024,    256>>>(W_UK,  wukh,  wukl);
    split_kernel<<<(DC * D_MODEL) / 1024,    256>>>(W_UV,  wuvh,  wuvl);
    split_kernel<<<(D_MODEL * DCQ) / 1024,   256>>>(W_DQ,  wdqh,  wdql);
    split_kernel<<<(DCQ * 2 * D_MODEL)/1024, 256>>>(W_UQ,  wuqh,  wuql);
    split_kernel<<<(D_MODEL * D_MODEL)/1024, 256>>>(W_out, wouth, woutl);

    // projections
    tc_gemm3<<<dim3(DC / 128, 16), 256>>>(xh, xl, wdkvh, wdkvl,
        nullptr, ckvh, ckvl, L_SEQ, DC, D_MODEL, 1);
    tc_gemm3<<<dim3(16, 16), 256>>>(ckvh, ckvl, wukh, wukl,
        kbuf, nullptr, nullptr, L_SEQ, D_MODEL, DC, 0);
    tc_gemm3<<<dim3(16, 16), 256>>>(ckvh, ckvl, wuvh, wuvl,
        nullptr, vh, vl, L_SEQ, D_MODEL, DC, 1);
    tc_gemm3<<<dim3(DCQ / 128, 16), 256>>>(xh, xl, wdqh, wdql,
        nullptr, cqh, cql, L_SEQ, DCQ, D_MODEL, 1);
    tc_gemm3<<<dim3(32, 16), 256>>>(cqh, cql, wuqh, wuql,
        qbuf, nullptr, nullptr, L_SEQ, 2 * D_MODEL, DCQ, 0);

    // RoPE (fp32)
    rope_kernel<<<dim3(L_SEQ, QHEADS), 64>>>(qbuf, 2 * D_MODEL);
    rope_kernel<<<dim3(L_SEQ, NHEADS), 64>>>(kbuf, D_MODEL);

    // K -> transposed hi/lo
    ktrans_split<<<dim3(L_SEQ / 32, 4, NHEADS), dim3(32, 8)>>>(kbuf, kth, ktl);

    // gate
    lam_kernel<<<L_SEQ, 256>>>(x, W_lam, b_lam, lam);

    // attention
    attn_tc3<<<dim3(L_SEQ / 128, QHEADS), 256, ATT_SMEM>>>(qbuf, kth, ktl, vh, vl, attn);

    // differential combine -> bf16 hi/lo
    combine_kernel2<<<(L_SEQ * D_MODEL / 2) / 256, 256>>>(attn, lam, cmbh, cmbl);

    // output projection
    tc_gemm3<<<dim3(16, 16), 256>>>(cmbh, cmbl, wouth, woutl,
        out, nullptr, nullptr, L_SEQ, D_MODEL, D_MODEL, 0);
}